// round 4
// baseline (speedup 1.0000x reference)
#include <cuda_runtime.h>
#include <math.h>
#include <stdint.h>
#include <stddef.h>

#define NN 50000
#define EE 800000
#define FF 128
#define HBITS 21
#define HSIZE (1u<<HBITS)
#define HMASK (HSIZE-1u)
#define NEGINF __int_as_float(0xff800000)

// ---------------- device scratch ----------------
__device__ float    g_z1[(size_t)NN*FF];
__device__ float    g_p2[(size_t)NN*FF];
__device__ float    g_feat[(size_t)NN*FF];
__device__ float    g_xp1[(size_t)NN*FF];
__device__ float    g_xp2[(size_t)NN*FF];
__device__ float    g_dinv1[NN],  g_dinv2[NN];
__device__ float    g_dcinv1[NN], g_dcinv2[NN];
__device__ float    g_m[NN];
__device__ int      g_pt1[NN], g_pt2[NN];
__device__ int      g_c1[NN], g_c2[NN];
__device__ float    g_cut[EE];
__device__ int      g_s2[EE];
__device__ int      g_d2[EE];
__device__ float    g_w2[EE];
__device__ unsigned g_hash[HSIZE];
// CSR (double buffered)
__device__ int      g_rp1[NN+1], g_rp2[NN+1];
__device__ int      g_cnt1[NN],  g_cnt2[NN];
__device__ int      g_bsum[256];
__device__ int      g_total;
__device__ int      g_col1[EE],  g_col2[EE];
__device__ float    g_val1[EE],  g_val2[EE];

__device__ __forceinline__ float eluf(float v){ return v > 0.f ? v : expm1f(v); }

// ---------------- CSR build ----------------
__global__ void k_count(const int* __restrict__ dst, const float* __restrict__ w,
                        int* __restrict__ cnt){
    int e = blockIdx.x*blockDim.x + threadIdx.x;
    if (e < EE && w[e] > 0.f) atomicAdd(&cnt[dst[e]], 1);
}
__global__ void k_scan1(const int* __restrict__ cnt, float* __restrict__ dcinv,
                        int* __restrict__ rp){
    __shared__ int s[256];
    int t = threadIdx.x;
    int i = blockIdx.x*256 + t;
    int v = (i < NN) ? cnt[i] : 0;
    if (i < NN) dcinv[i] = v > 0 ? 1.0f/(float)v : 0.f;
    s[t] = v; __syncthreads();
    #pragma unroll
    for (int off = 1; off < 256; off <<= 1){
        int tv = (t >= off) ? s[t-off] : 0;
        __syncthreads();
        s[t] += tv;
        __syncthreads();
    }
    if (i < NN) rp[i] = s[t] - v;
    if (t == 255) g_bsum[blockIdx.x] = s[255];
}
__global__ void k_scan2(){
    __shared__ int s[256];
    int t = threadIdx.x;
    int v = (t < 196) ? g_bsum[t] : 0;
    s[t] = v; __syncthreads();
    #pragma unroll
    for (int off = 1; off < 256; off <<= 1){
        int tv = (t >= off) ? s[t-off] : 0;
        __syncthreads();
        s[t] += tv;
        __syncthreads();
    }
    if (t < 196) g_bsum[t] = s[t] - v;
    if (t == 255) g_total = s[255];
}
__global__ void k_scan3(int* __restrict__ rp, int* __restrict__ pt){
    int i = blockIdx.x*256 + threadIdx.x;
    if (i < NN){
        rp[i] += g_bsum[blockIdx.x];
        g_m[i] = NEGINF;
        pt[i] = -1;
    }
    if (i == 0) rp[NN] = g_total;
}
__global__ void k_fill(const int* __restrict__ src, const int* __restrict__ dst,
                       const float* __restrict__ w,
                       const int* __restrict__ rp, int* __restrict__ cnt,
                       const float* __restrict__ dcinv,
                       int* __restrict__ col, float* __restrict__ val){
    int e = blockIdx.x*blockDim.x + threadIdx.x;
    if (e >= EE) return;
    int s = src[e], d = dst[e];
    float wv = w[e];
    float cut;
    if (wv > 0.f){
        int pos = rp[d] + atomicAdd(&cnt[d], 1);
        col[pos] = s;
        val[pos] = wv;
        cut = wv * (dcinv[s] + dcinv[d]);
        atomicMax(reinterpret_cast<int*>(&g_m[s]), __float_as_int(cut));
    } else {
        cut = NEGINF;
    }
    g_cut[e] = cut;
}
__global__ void __launch_bounds__(256) k_rowsum(const int* __restrict__ rp,
                                                const float* __restrict__ val,
                                                float* __restrict__ dinv){
    int node = (blockIdx.x*blockDim.x + threadIdx.x) >> 5;
    int l = threadIdx.x & 31;
    if (node >= NN) return;
    int beg = rp[node], end = rp[node+1];
    float sum = 0.f;
    for (int e = beg + l; e < end; e += 32) sum += val[e];
    #pragma unroll
    for (int off = 16; off > 0; off >>= 1) sum += __shfl_xor_sync(0xFFFFFFFFu, sum, off);
    if (l == 0) dinv[node] = sum > 0.f ? rsqrtf(sum) : 0.f;
}
__global__ void __launch_bounds__(256) k_norm(const int* __restrict__ rp,
                                              const int* __restrict__ col,
                                              float* __restrict__ val,
                                              const float* __restrict__ dinv){
    int node = (blockIdx.x*blockDim.x + threadIdx.x) >> 5;
    int l = threadIdx.x & 31;
    if (node >= NN) return;
    int beg = rp[node], end = rp[node+1];
    float di = -dinv[node];
    for (int e = beg + l; e < end; e += 32)
        val[e] = di * dinv[col[e]] * val[e];
}

// ---------------- prop: pure gather, warp per node, 4-way ILP ----------------
__global__ void __launch_bounds__(256) k_prop(const int* __restrict__ rp,
                                              const int* __restrict__ col,
                                              const float* __restrict__ val,
                                              const float* __restrict__ zin,
                                              float* __restrict__ zout){
    int node = (blockIdx.x*blockDim.x + threadIdx.x) >> 5;
    int l = threadIdx.x & 31;
    if (node >= NN) return;
    int beg = rp[node], end = rp[node+1];
    const float4* z4 = reinterpret_cast<const float4*>(zin);
    float4 a0 = make_float4(0.f,0.f,0.f,0.f);
    float4 a1 = a0, a2 = a0, a3 = a0;
    int e = beg;
    for (; e + 4 <= end; e += 4){
        int   s0 = __ldg(&col[e  ]), s1 = __ldg(&col[e+1]);
        int   s2 = __ldg(&col[e+2]), s3 = __ldg(&col[e+3]);
        float c0 = __ldg(&val[e  ]), c1 = __ldg(&val[e+1]);
        float c2 = __ldg(&val[e+2]), c3 = __ldg(&val[e+3]);
        float4 v0 = z4[(size_t)s0*(FF/4) + l];
        float4 v1 = z4[(size_t)s1*(FF/4) + l];
        float4 v2 = z4[(size_t)s2*(FF/4) + l];
        float4 v3 = z4[(size_t)s3*(FF/4) + l];
        a0.x = fmaf(c0,v0.x,a0.x); a0.y = fmaf(c0,v0.y,a0.y);
        a0.z = fmaf(c0,v0.z,a0.z); a0.w = fmaf(c0,v0.w,a0.w);
        a1.x = fmaf(c1,v1.x,a1.x); a1.y = fmaf(c1,v1.y,a1.y);
        a1.z = fmaf(c1,v1.z,a1.z); a1.w = fmaf(c1,v1.w,a1.w);
        a2.x = fmaf(c2,v2.x,a2.x); a2.y = fmaf(c2,v2.y,a2.y);
        a2.z = fmaf(c2,v2.z,a2.z); a2.w = fmaf(c2,v2.w,a2.w);
        a3.x = fmaf(c3,v3.x,a3.x); a3.y = fmaf(c3,v3.y,a3.y);
        a3.z = fmaf(c3,v3.z,a3.z); a3.w = fmaf(c3,v3.w,a3.w);
    }
    for (; e < end; e++){
        int   s0 = __ldg(&col[e]);
        float c0 = __ldg(&val[e]);
        float4 v0 = z4[(size_t)s0*(FF/4) + l];
        a0.x = fmaf(c0,v0.x,a0.x); a0.y = fmaf(c0,v0.y,a0.y);
        a0.z = fmaf(c0,v0.z,a0.z); a0.w = fmaf(c0,v0.w,a0.w);
    }
    float4 acc;
    acc.x = (a0.x+a1.x)+(a2.x+a3.x);
    acc.y = (a0.y+a1.y)+(a2.y+a3.y);
    acc.z = (a0.z+a1.z)+(a2.z+a3.z);
    acc.w = (a0.w+a1.w)+(a2.w+a3.w);
    reinterpret_cast<float4*>(zout)[(size_t)node*(FF/4) + l] = acc;
}

// ---------------- GEMM part: out (+)= zpart @ W[128x128]; mode2 adds bias+ELU ----------------
// mode 0: out  = zA @ W                (first part, plain write)
// mode 1: out += zA @ W                (accumulate)
// mode 2: out  = elu(out + (2*zA - zB) @ W + b)   (final part)
#define MT 64
#define KC 32
#define LDZ 68
__global__ void __launch_bounds__(256) k_gemm_part(const float* __restrict__ zA,
                                                   const float* __restrict__ zB,
                                                   const float* __restrict__ W,
                                                   const float* __restrict__ bv,
                                                   float* __restrict__ out,
                                                   int mode){
    __shared__ float sZ[KC*LDZ];
    __shared__ float sW[KC*FF];
    int tid = threadIdx.x;
    int row0 = blockIdx.x * MT;
    int cg = tid & 31, rg = tid >> 5;
    float acc[8][4];
    #pragma unroll
    for (int r=0;r<8;r++){ acc[r][0]=0.f; acc[r][1]=0.f; acc[r][2]=0.f; acc[r][3]=0.f; }

    const float4* W4 = reinterpret_cast<const float4*>(W);
    for (int ch = 0; ch < 4; ch++){
        int kloc = ch * KC;
        __syncthreads();
        #pragma unroll
        for (int q=0;q<2;q++){
            int i   = tid + 256*q;
            int row = i >> 3;
            int seg = i & 7;
            int grow = row0 + row;
            float4 v = make_float4(0.f,0.f,0.f,0.f);
            if (grow < NN){
                v = *reinterpret_cast<const float4*>(zA + (size_t)grow*FF + kloc + seg*4);
                if (mode == 2){
                    float4 a = *reinterpret_cast<const float4*>(zB + (size_t)grow*FF + kloc + seg*4);
                    v.x = 2.f*v.x - a.x; v.y = 2.f*v.y - a.y;
                    v.z = 2.f*v.z - a.z; v.w = 2.f*v.w - a.w;
                }
            }
            int kk = seg*4;
            sZ[(kk+0)*LDZ+row] = v.x; sZ[(kk+1)*LDZ+row] = v.y;
            sZ[(kk+2)*LDZ+row] = v.z; sZ[(kk+3)*LDZ+row] = v.w;
        }
        #pragma unroll
        for (int q=0;q<4;q++){
            int i = tid + 256*q;
            reinterpret_cast<float4*>(sW)[i] = W4[(size_t)kloc*(FF/4) + i];
        }
        __syncthreads();
        #pragma unroll
        for (int kk=0; kk<KC; kk++){
            float4 w4 = *reinterpret_cast<const float4*>(sW + kk*FF + cg*4);
            const float* zr = sZ + kk*LDZ + rg*8;
            float4 za = *reinterpret_cast<const float4*>(zr);
            float4 zb = *reinterpret_cast<const float4*>(zr+4);
            float zv[8] = {za.x,za.y,za.z,za.w,zb.x,zb.y,zb.z,zb.w};
            #pragma unroll
            for (int r=0;r<8;r++){
                acc[r][0] = fmaf(zv[r], w4.x, acc[r][0]);
                acc[r][1] = fmaf(zv[r], w4.y, acc[r][1]);
                acc[r][2] = fmaf(zv[r], w4.z, acc[r][2]);
                acc[r][3] = fmaf(zv[r], w4.w, acc[r][3]);
            }
        }
    }
    float4 b4 = make_float4(0.f,0.f,0.f,0.f);
    if (mode == 2) b4 = *reinterpret_cast<const float4*>(bv + cg*4);
    #pragma unroll
    for (int r=0;r<8;r++){
        int grow = row0 + rg*8 + r;
        if (grow < NN){
            float4 o = make_float4(acc[r][0], acc[r][1], acc[r][2], acc[r][3]);
            float4* op = reinterpret_cast<float4*>(out + (size_t)grow*FF + cg*4);
            if (mode >= 1){
                float4 prev = *op;
                o.x += prev.x; o.y += prev.y; o.z += prev.z; o.w += prev.w;
            }
            if (mode == 2){
                o.x = eluf(o.x + b4.x); o.y = eluf(o.y + b4.y);
                o.z = eluf(o.z + b4.z); o.w = eluf(o.w + b4.w);
            }
            *op = o;
        }
    }
}

// ---------------- graclus matching ----------------
__global__ void k_partner(const int* __restrict__ src, const int* __restrict__ dst,
                          int* __restrict__ pt){
    int e = blockIdx.x*blockDim.x + threadIdx.x;
    if (e >= EE) return;
    float c = g_cut[e];
    int s = src[e];
    if (c > NEGINF && c == g_m[s])
        atomicMax(&pt[s], dst[e]);
}
__global__ void k_cluster(const int* __restrict__ pt, int* __restrict__ cl){
    int i = blockIdx.x*blockDim.x + threadIdx.x;
    if (i >= NN) return;
    int p = pt[i];
    int c = i;
    if (p >= 0 && p != i && pt[p] == i) c = min(i, p);
    cl[i] = c;
}

// ---------------- pool_x ----------------
__global__ void k_pool(const int* __restrict__ pt,
                       const float* __restrict__ x, float* __restrict__ xp){
    int t = blockIdx.x*blockDim.x + threadIdx.x;
    int j = t >> 5, l = t & 31;
    if (j >= NN) return;
    int p = pt[j];
    bool mut = (p >= 0 && p != j && pt[p] == j);
    float4 o;
    if (mut && p < j){
        o = make_float4(0.f,0.f,0.f,0.f);
    } else {
        float4 a = reinterpret_cast<const float4*>(x + (size_t)j*FF)[l];
        if (mut){
            float4 b = reinterpret_cast<const float4*>(x + (size_t)p*FF)[l];
            a.x = fmaxf(a.x,b.x); a.y = fmaxf(a.y,b.y);
            a.z = fmaxf(a.z,b.z); a.w = fmaxf(a.w,b.w);
        }
        o = a;
    }
    reinterpret_cast<float4*>(xp + (size_t)j*FF)[l] = o;
}

// ---------------- pooled edges ----------------
__global__ void k_pool_edges(const int* __restrict__ src, const int* __restrict__ dst){
    int e = blockIdx.x*blockDim.x + threadIdx.x;
    if (e >= EE) return;
    int s = g_c1[src[e]], d = g_c1[dst[e]];
    g_s2[e] = s; g_d2[e] = d;
    float w = 0.f;
    if (s != d){
        unsigned key = (unsigned)s * (unsigned)NN + (unsigned)d;
        unsigned h = (key * 2654435761u) >> (32 - HBITS);
        h &= HMASK;
        while (true){
            unsigned old = atomicCAS(&g_hash[h], 0xFFFFFFFFu, key);
            if (old == 0xFFFFFFFFu){ w = 1.f; break; }
            if (old == key){ w = 0.f; break; }
            h = (h + 1u) & HMASK;
        }
    }
    g_w2[e] = w;
}

// ---------------- fused log_softmax + gather ----------------
__global__ void k_smax_gather(float* __restrict__ outp){
    int t = blockIdx.x*blockDim.x + threadIdx.x;
    int i = t >> 5, l = t & 31;
    if (i >= NN) return;
    int r = g_c2[g_c1[i]];
    float4 v = reinterpret_cast<const float4*>(g_xp2 + (size_t)r*FF)[l];
    float mx = fmaxf(fmaxf(v.x,v.y), fmaxf(v.z,v.w));
    #pragma unroll
    for (int off=16; off>0; off>>=1) mx = fmaxf(mx, __shfl_xor_sync(0xFFFFFFFFu, mx, off));
    float s = expf(v.x-mx)+expf(v.y-mx)+expf(v.z-mx)+expf(v.w-mx);
    #pragma unroll
    for (int off=16; off>0; off>>=1) s += __shfl_xor_sync(0xFFFFFFFFu, s, off);
    float lse = mx + logf(s);
    v.x -= lse; v.y -= lse; v.z -= lse; v.w -= lse;
    reinterpret_cast<float4*>(outp + (size_t)i*FF)[l] = v;
}

// ---------------- host ----------------
static void* symaddr(const void* s){ void* p = nullptr; cudaGetSymbolAddress(&p, s); return p; }

extern "C" void kernel_launch(void* const* d_in, const int* in_sizes, int n_in,
                              void* d_out, int out_size) {
    const float* x  = (const float*)d_in[0];
    const float* ew = (const float*)d_in[1];
    const float* W1 = (const float*)d_in[2];
    const float* b1 = (const float*)d_in[3];
    const float* W2 = (const float*)d_in[4];
    const float* b2 = (const float*)d_in[5];
    const int*   ei = (const int*)  d_in[6];
    const int* src = ei;
    const int* dst = ei + EE;
    float* outp = (float*)d_out;

    float* z1   = (float*) symaddr(g_z1);
    float* p2   = (float*) symaddr(g_p2);
    float* feat = (float*) symaddr(g_feat);
    float* xp1  = (float*) symaddr(g_xp1);
    float* xp2  = (float*) symaddr(g_xp2);
    int*   cnt1 = (int*)   symaddr(g_cnt1);
    int*   cnt2 = (int*)   symaddr(g_cnt2);
    void*  hash = symaddr(g_hash);
    int*   c1   = (int*)   symaddr(g_c1);
    int*   c2   = (int*)   symaddr(g_c2);
    int*   s2   = (int*)   symaddr(g_s2);
    int*   d2   = (int*)   symaddr(g_d2);
    float* w2   = (float*) symaddr(g_w2);
    int*   rp1  = (int*)   symaddr(g_rp1);
    int*   rp2  = (int*)   symaddr(g_rp2);
    int*   col1 = (int*)   symaddr(g_col1);
    int*   col2 = (int*)   symaddr(g_col2);
    float* val1 = (float*) symaddr(g_val1);
    float* val2 = (float*) symaddr(g_val2);
    float* di1  = (float*) symaddr(g_dinv1);
    float* di2  = (float*) symaddr(g_dinv2);
    float* dc1  = (float*) symaddr(g_dcinv1);
    float* dc2  = (float*) symaddr(g_dcinv2);
    int*   pt1  = (int*)   symaddr(g_pt1);
    int*   pt2  = (int*)   symaddr(g_pt2);

    static cudaStream_t sB = nullptr, sC = nullptr;
    static cudaEvent_t evRoot, evFill, evC1, evB2, evZ1, evP1, evPool1, evZ2, evP12;
    if (!sB){
        cudaStreamCreate(&sB);
        cudaStreamCreate(&sC);
        cudaEventCreateWithFlags(&evRoot,  cudaEventDisableTiming);
        cudaEventCreateWithFlags(&evFill,  cudaEventDisableTiming);
        cudaEventCreateWithFlags(&evC1,    cudaEventDisableTiming);
        cudaEventCreateWithFlags(&evB2,    cudaEventDisableTiming);
        cudaEventCreateWithFlags(&evZ1,    cudaEventDisableTiming);
        cudaEventCreateWithFlags(&evP1,    cudaEventDisableTiming);
        cudaEventCreateWithFlags(&evPool1, cudaEventDisableTiming);
        cudaEventCreateWithFlags(&evZ2,    cudaEventDisableTiming);
        cudaEventCreateWithFlags(&evP12,   cudaEventDisableTiming);
    }

    const int EB = EE/256;
    const int NB = (NN+255)/256;
    const int PB = (NN*32+255)/256;
    const int GB = (NN+MT-1)/MT;

    // ===== A: block-1 CSR build =====
    cudaMemsetAsync(cnt1, 0, NN*sizeof(int));
    cudaEventRecord(evRoot, 0);
    k_count<<<EB,256>>>(dst, ew, cnt1);
    k_scan1<<<NB,256>>>(cnt1, dc1, rp1);
    k_scan2<<<1,256>>>();
    k_scan3<<<NB,256>>>(rp1, pt1);
    cudaMemsetAsync(cnt1, 0, NN*sizeof(int));
    k_fill<<<EB,256>>>(src, dst, ew, rp1, cnt1, dc1, col1, val1);
    cudaEventRecord(evFill, 0);

    // ===== C: gemm1 part0 = x @ W1[0] (overlaps CSR build + prop1a) =====
    cudaStreamWaitEvent(sC, evRoot, 0);
    k_gemm_part<<<GB,256,0,sC>>>(x, nullptr, W1, nullptr, feat, 0);

    // ===== B: matching + pooled-graph CSR (hidden under A) =====
    cudaStreamWaitEvent(sB, evFill, 0);
    k_partner<<<EB,256,0,sB>>>(src, dst, pt1);
    k_cluster<<<NB,256,0,sB>>>(pt1, c1);
    cudaEventRecord(evC1, sB);
    cudaMemsetAsync(hash, 0xFF, HSIZE*sizeof(unsigned), sB);
    k_pool_edges<<<EB,256,0,sB>>>(src, dst);
    cudaMemsetAsync(cnt2, 0, NN*sizeof(int), sB);
    k_count<<<EB,256,0,sB>>>(d2, w2, cnt2);
    k_scan1<<<NB,256,0,sB>>>(cnt2, dc2, rp2);
    k_scan2<<<1,256,0,sB>>>();
    k_scan3<<<NB,256,0,sB>>>(rp2, pt2);
    cudaMemsetAsync(cnt2, 0, NN*sizeof(int), sB);
    k_fill<<<EB,256,0,sB>>>(s2, d2, w2, rp2, cnt2, dc2, col2, val2);
    k_rowsum<<<PB,256,0,sB>>>(rp2, val2, di2);
    k_norm<<<PB,256,0,sB>>>(rp2, col2, val2, di2);
    k_partner<<<EB,256,0,sB>>>(s2, d2, pt2);
    k_cluster<<<NB,256,0,sB>>>(pt2, c2);
    cudaEventRecord(evB2, sB);

    // ===== A: block-1 heavy chain =====
    k_rowsum<<<PB,256>>>(rp1, val1, di1);
    k_norm<<<PB,256>>>(rp1, col1, val1, di1);
    k_prop<<<PB,256>>>(rp1, col1, val1, x, z1);
    cudaEventRecord(evZ1, 0);

    // C: gemm1 part1 = feat += z1 @ W1[1]  (overlaps prop1b)
    cudaStreamWaitEvent(sC, evZ1, 0);
    k_gemm_part<<<GB,256,0,sC>>>(z1, nullptr, W1 + 128*128, nullptr, feat, 1);
    cudaEventRecord(evP1, sC);

    k_prop<<<PB,256>>>(rp1, col1, val1, z1, p2);
    // A: gemm1 part2 = elu(feat + (2*p2 - x) @ W1[2] + b1)
    cudaStreamWaitEvent(0, evP1, 0);
    k_gemm_part<<<GB,256>>>(p2, x, W1 + 2*128*128, b1, feat, 2);
    cudaStreamWaitEvent(0, evC1, 0);
    k_pool<<<PB,256>>>(pt1, feat, xp1);
    cudaEventRecord(evPool1, 0);

    // C: gemm2 part0 = feat = xp1 @ W2[0]  (overlaps prop2a)
    cudaStreamWaitEvent(sC, evPool1, 0);
    k_gemm_part<<<GB,256,0,sC>>>(xp1, nullptr, W2, nullptr, feat, 0);

    // ===== A: block-2 heavy chain =====
    cudaStreamWaitEvent(0, evB2, 0);
    k_prop<<<PB,256>>>(rp2, col2, val2, xp1, z1);
    cudaEventRecord(evZ2, 0);

    // C: gemm2 part1 = feat += z1 @ W2[1]  (overlaps prop2b)
    cudaStreamWaitEvent(sC, evZ2, 0);
    k_gemm_part<<<GB,256,0,sC>>>(z1, nullptr, W2 + 128*128, nullptr, feat, 1);
    cudaEventRecord(evP12, sC);

    k_prop<<<PB,256>>>(rp2, col2, val2, z1, p2);
    cudaStreamWaitEvent(0, evP12, 0);
    k_gemm_part<<<GB,256>>>(p2, xp1, W2 + 2*128*128, b2, feat, 2);
    k_pool<<<PB,256>>>(pt2, feat, xp2);

    // ===== output =====
    k_smax_gather<<<PB,256>>>(outp);
}